// round 9
// baseline (speedup 1.0000x reference)
#include <cuda_runtime.h>
#include <cstdint>

// ShapeletNet via HMMA bf16-split GEMM, register-staged (no f32 smem leg).
// Thread t owns A row t: LDG f32 (chunk c+1, double-buffered in registers)
// -> convert bf16 hi/lo -> STS -> warp-local ldmatrix + mma. Main loop is
// __syncwarp-only (A tile warp-private).
// Math: A row (k16) = [bf16hi(x) 8d | bf16lo(x) 8d];
//   B1 = [qh|qh] -> xh*qh + xl*qh ; B2 = [ql|0] -> xh*ql (xl*ql dropped ~2^-16)
// dist[p] = QQ + XX[p] - 2*QX[p]; per-segment min; last-done block: scale+Linear.

#define DFEAT 64
#define MLEN 32
#define TT 512
#define NT 512
#define DCH 8
#define NCHUNK 8
#define SSTRIDE 33
#define ASTR 48

// byte offsets in dynamic smem
#define A_OFF    0          // 512 rows x 48B = 24576
#define QB_OFF   24576      // 8 chunks x (B1 2KB + B2 2KB) = 32768 -> ends 57344
#define CS2_OFF  67584      // after Sbuf region (512*33*4 = 67584)
#define RED_OFF  69632      // 64 f32
#define SMEM_BYTES 69952
// Sbuf[0, 67584) aliases A+QB after the GEMM completes

__device__ float g_mins[8192];
__device__ int   g_count;

extern __shared__ __align__(1024) float smf[];

__device__ __forceinline__ uint32_t smem_u32(const void* p) {
    uint32_t a;
    asm("{ .reg .u64 t; cvta.to.shared.u64 t, %1; cvt.u32.u64 %0, t; }" : "=r"(a) : "l"(p));
    return a;
}
// pack: result.hi = bf16(a), result.lo = bf16(b)
__device__ __forceinline__ uint32_t packbf(float a, float b) {
    uint32_t r;
    asm("cvt.rn.bf16x2.f32 %0, %1, %2;" : "=r"(r) : "f"(a), "f"(b));
    return r;
}
#define STS128(r0, r1, r2, r3, addr) \
    asm volatile("st.shared.v4.b32 [%0], {%1, %2, %3, %4};" \
                 :: "r"(addr), "r"(r0), "r"(r1), "r"(r2), "r"(r3) : "memory")

__device__ __forceinline__ void ldmA(uint32_t* a, uint32_t addr) {
    asm volatile("ldmatrix.sync.aligned.m8n8.x4.shared.b16 {%0,%1,%2,%3}, [%4];"
                 : "=r"(a[0]), "=r"(a[1]), "=r"(a[2]), "=r"(a[3]) : "r"(addr));
}
__device__ __forceinline__ void ldmB(uint32_t* b, uint32_t addr) {
    asm volatile("ldmatrix.sync.aligned.m8n8.x2.shared.b16 {%0,%1}, [%2];"
                 : "=r"(b[0]), "=r"(b[1]) : "r"(addr));
}
__device__ __forceinline__ uint32_t ldmB1(uint32_t addr) {
    uint32_t b0;
    asm volatile("ldmatrix.sync.aligned.m8n8.x1.shared.b16 {%0}, [%1];"
                 : "=r"(b0) : "r"(addr));
    return b0;
}
__device__ __forceinline__ void mma16816(float* c, const uint32_t* a, const uint32_t* b) {
    asm volatile("mma.sync.aligned.m16n8k16.row.col.f32.bf16.bf16.f32 "
                 "{%0,%1,%2,%3}, {%4,%5,%6,%7}, {%8,%9}, {%0,%1,%2,%3};"
                 : "+f"(c[0]), "+f"(c[1]), "+f"(c[2]), "+f"(c[3])
                 : "r"(a[0]), "r"(a[1]), "r"(a[2]), "r"(a[3]), "r"(b[0]), "r"(b[1]));
}
__device__ __forceinline__ uint32_t gpos(int r, int g) {
    return (uint32_t)(g ^ ((r >> 1) & 3));
}

__global__ __launch_bounds__(NT, 2)
void shapelet_kernel(const float* __restrict__ X,
                     const float* __restrict__ q,
                     const int* __restrict__ cumlens,
                     const float* __restrict__ lin_w,
                     const float* __restrict__ lin_b,
                     float* __restrict__ out,
                     long long T, int n_seg)
{
    const uint32_t smb = smem_u32(smf);
    float* cs2p = smf + CS2_OFF / 4;
    float* redf = smf + RED_OFF / 4;
    float* Sbuf = smf;

    const int tid  = threadIdx.x;
    const int w    = tid >> 5;
    const int lane = tid & 31;
    const int l15  = lane & 15;

    const int seg = blockIdx.x;
    const long long c0 = (long long)cumlens[seg];
    int len = cumlens[seg + 1] - (int)c0;
    if (len > TT) len = TT;
    if (len < 0) len = 0;

    const bool ok = tid < len;
    const float* xcol = X + c0 + tid;

    // ---- preload chunk 0 into registers ----
    float xn[8];
#pragma unroll
    for (int k = 0; k < 8; k++)
        xn[k] = ok ? xcol[(long long)k * T] : 0.f;

    // ---- Q staging: warp w (w<8) builds B1+B2 for chunk w, + QQ partials ----
    if (w < 8) {
        const int j = lane;
        float qq = 0.f;
        uint32_t h[4], l[4];
#pragma unroll
        for (int k = 0; k < 4; k++) {
            int d = 8 * w + 2 * k;
            float qe = q[d * MLEN + j];
            float qo = q[(d + 1) * MLEN + j];
            qq = fmaf(qe, qe, qq);
            qq = fmaf(qo, qo, qq);
            uint32_t hp = packbf(qo, qe);
            float fe = __uint_as_float(hp << 16);
            float fo = __uint_as_float(hp & 0xffff0000u);
            h[k] = hp;
            l[k] = packbf(qo - fo, qe - fe);
        }
        uint32_t b1 = smb + QB_OFF + (uint32_t)w * 4096u + (uint32_t)j * 64u;
        uint32_t b2 = b1 + 2048u;
#pragma unroll
        for (int g = 0; g < 4; g++)
            STS128(h[0], h[1], h[2], h[3], b1 + gpos(j, g) * 16u);
        STS128(l[0], l[1], l[2], l[3], b2 + gpos(j, 0) * 16u);
        STS128(0u, 0u, 0u, 0u,          b2 + gpos(j, 1) * 16u);
        STS128(0u, 0u, 0u, 0u,          b2 + gpos(j, 2) * 16u);
        STS128(0u, 0u, 0u, 0u,          b2 + gpos(j, 3) * 16u);
#pragma unroll
        for (int o = 16; o; o >>= 1) qq += __shfl_down_sync(0xffffffffu, qq, o);
        if (lane == 0) redf[40 + w] = qq;
    }
    __syncthreads();     // QB + QQ visible; only block barrier before GEMM
    float QQ = 0.f;
#pragma unroll
    for (int k = 0; k < 8; k++) QQ += redf[40 + k];

    // ---- accumulators: warp owns t in [32w, 32w+32): 2 m x 4 n tiles ----
    float acc[2][4][4];
#pragma unroll
    for (int m = 0; m < 2; m++)
#pragma unroll
        for (int n = 0; n < 4; n++)
#pragma unroll
            for (int k = 0; k < 4; k++) acc[m][n][k] = 0.f;

    float cs = 0.f;
    const uint32_t arow = smb + A_OFF + (uint32_t)tid * ASTR;
    const uint32_t a_w  = smb + A_OFF + (uint32_t)(32 * w) * ASTR;

#pragma unroll
    for (int c = 0; c < NCHUNK; c++) {
        // take current chunk values; start next chunk's LDGs immediately
        float xc[8];
#pragma unroll
        for (int k = 0; k < 8; k++) xc[k] = xn[k];
        if (c + 1 < NCHUNK) {
#pragma unroll
            for (int k = 0; k < 8; k++)
                xn[k] = ok ? xcol[(long long)((c + 1) * DCH + k) * T] : 0.f;
        }

        // ---- convert (registers): f32 -> bf16 hi/lo A row t = tid ----
        {
            uint32_t h[4], l[4];
#pragma unroll
            for (int k = 0; k < 4; k++) {
                float xe = xc[2 * k], xo = xc[2 * k + 1];
                cs = fmaf(xe, xe, cs);
                cs = fmaf(xo, xo, cs);
                uint32_t hp = packbf(xo, xe);
                float fe = __uint_as_float(hp << 16);
                float fo = __uint_as_float(hp & 0xffff0000u);
                h[k] = hp;
                l[k] = packbf(xo - fo, xe - fe);
            }
            STS128(h[0], h[1], h[2], h[3], arow);
            STS128(l[0], l[1], l[2], l[3], arow + 16u);
        }
        __syncwarp();

        // ---- MMA chunk c (warp-local A, shared read-only B) ----
        {
            const uint32_t qb1 = smb + QB_OFF + (uint32_t)c * 4096u;
            const uint32_t qb2 = qb1 + 2048u;
            uint32_t B1[4][2], B2[4][2];
#pragma unroll
            for (int n = 0; n < 4; n++) {
                int r = 8 * n + (l15 & 7);
                int g = l15 >> 3;
                ldmB(B1[n], qb1 + (uint32_t)r * 64u + gpos(r, g) * 16u);
                // B2 granule1 is all zeros: x1 load + literal 0
                int r2 = 8 * n + (lane & 7);
                B2[n][0] = ldmB1(qb2 + (uint32_t)r2 * 64u + gpos(r2, 0) * 16u);
                B2[n][1] = 0u;
            }
#pragma unroll
            for (int m = 0; m < 2; m++) {
                uint32_t A[4];
                ldmA(A, a_w + (uint32_t)(16 * m + l15) * ASTR + (uint32_t)(lane >> 4) * 16u);
#pragma unroll
                for (int n = 0; n < 4; n++) {
                    mma16816(acc[m][n], A, B1[n]);
                    mma16816(acc[m][n], A, B2[n]);
                }
            }
        }
        __syncwarp();
    }

    cs2p[tid] = cs;
    __syncthreads();       // all warps done with A/QB; Sbuf alias safe

    // ---- scatter S fragments to Sbuf[512][33] ----
    {
        const int rbase = 32 * w + (lane >> 2);
        const int cbase = 2 * (lane & 3);
#pragma unroll
        for (int m = 0; m < 2; m++) {
#pragma unroll
            for (int n = 0; n < 4; n++) {
                int r = rbase + 16 * m;
                int cc = cbase + 8 * n;
                Sbuf[r * SSTRIDE + cc]           = acc[m][n][0];
                Sbuf[r * SSTRIDE + cc + 1]       = acc[m][n][1];
                Sbuf[(r + 8) * SSTRIDE + cc]     = acc[m][n][2];
                Sbuf[(r + 8) * SSTRIDE + cc + 1] = acc[m][n][3];
            }
        }
    }
    __syncthreads();

    // ---- gather: QX[p], dist, segment min ----
    const int nwin = len - MLEN + 1;
    float lmin = 3e38f;
    if (tid < nwin) {
        float qx = 0.f, xx = 0.f;
#pragma unroll
        for (int j = 0; j < MLEN; j++) {
            qx += Sbuf[(tid + j) * SSTRIDE + j];
            xx += cs2p[tid + j];
        }
        lmin = QQ + xx - 2.f * qx;
    }
#pragma unroll
    for (int o = 16; o; o >>= 1) lmin = fminf(lmin, __shfl_down_sync(0xffffffffu, lmin, o));
    __syncthreads();
    if (lane == 0) redf[w] = lmin;
    __syncthreads();
    if (tid == 0) {
        float m = redf[0];
#pragma unroll
        for (int ww = 1; ww < NT / 32; ww++) m = fminf(m, redf[ww]);
        g_mins[seg] = m;
    }

    // ---- last-block-done epilogue ----
    int* flagp = (int*)(redf + 33);
    __threadfence();
    __syncthreads();
    if (tid == 0) {
        int old = atomicAdd(&g_count, 1);
        *flagp = (old == gridDim.x - 1) ? 1 : 0;
    }
    __syncthreads();
    if (!*flagp) return;
    __threadfence();

    float lo = 3e38f, hi = -3e38f;
    for (int i = tid; i < n_seg; i += NT) {
        float v = g_mins[i];
        lo = fminf(lo, v);
        hi = fmaxf(hi, v);
    }
#pragma unroll
    for (int o = 16; o; o >>= 1) {
        lo = fminf(lo, __shfl_down_sync(0xffffffffu, lo, o));
        hi = fmaxf(hi, __shfl_down_sync(0xffffffffu, hi, o));
    }
    __syncthreads();
    if (lane == 0) { redf[w] = lo; redf[16 + w] = hi; }
    __syncthreads();
    if (tid == 0) {
        float l = redf[0], h = redf[16];
#pragma unroll
        for (int ww = 1; ww < NT / 32; ww++) { l = fminf(l, redf[ww]); h = fmaxf(h, redf[16 + ww]); }
        redf[34] = l; redf[35] = h;
        g_count = 0;
    }
    __syncthreads();
    const float flo = redf[34], fhi = redf[35];
    const float w0 = lin_w[0], w1 = lin_w[1];
    const float b0 = lin_b[0], b1 = lin_b[1];
    const float inv = 1.f / (fhi - flo + 1e-16f);
    for (int i = tid; i < n_seg; i += NT) {
        float s = (g_mins[i] - flo) * inv;
        out[2 * i]     = fmaf(s, w0, b0);
        out[2 * i + 1] = fmaf(s, w1, b1);
    }
}

extern "C" void kernel_launch(void* const* d_in, const int* in_sizes, int n_in,
                              void* d_out, int out_size)
{
    const float* X   = (const float*)d_in[0];
    const float* q   = (const float*)d_in[1];
    const float* lw  = (const float*)d_in[2];
    const float* lb  = (const float*)d_in[3];
    const int*   cum = (const int*)d_in[4];

    const int n_seg = in_sizes[4] - 1;
    const long long T = (long long)in_sizes[0] / DFEAT;

    cudaFuncSetAttribute(shapelet_kernel,
                         cudaFuncAttributeMaxDynamicSharedMemorySize, SMEM_BYTES);

    shapelet_kernel<<<n_seg, NT, SMEM_BYTES>>>(X, q, cum, lw, lb, (float*)d_out, T, n_seg);
}

// round 10
// speedup vs baseline: 1.1839x; 1.1839x over previous
#include <cuda_runtime.h>
#include <cstdint>

// ShapeletNet via HMMA bf16-split GEMM. cp.async f32 staging (warp-private,
// double-buffered); A fragments built DIRECTLY in registers from staging LDS
// (no bf16 A smem tile, no STS/ldmatrix for A). B (query) staged once, read
// via ldmatrix. Main loop: 1 __syncwarp per chunk, no __syncthreads.
// Math: A row (k16) = [bf16hi(x) 8d | bf16lo(x) 8d];
//   B1 = [qh|qh] -> xh*qh + xl*qh ; B2 = [ql|0] -> xh*ql (xl*ql dropped ~2^-16)
// dist[p] = QQ + XX[p] - 2*QX[p]; per-segment min; last-done block: scale+Linear.

#define DFEAT 64
#define MLEN 32
#define TT 512
#define NT 512
#define DCH 8
#define NCHUNK 8
#define SSTRIDE 33
#define XFSTR 36            // staging row stride in floats (bank-spread pad)

// byte offsets in dynamic smem
#define XF_OFF   0          // 2 bufs x 16 warps x 8 rows x 144B = 36864
#define QB_OFF   36864      // 8 chunks x (B1 2KB + B2 2KB) = 32768 -> 69632
#define CS2_OFF  69632      // 512 f32 -> 71680
#define RED_OFF  71680      // 64 f32  -> 71936
#define SMEM_BYTES 71936
// Sbuf[0, 67584) aliases XF+QB-head after the GEMM completes

__device__ float g_mins[8192];
__device__ int   g_count;

extern __shared__ __align__(1024) float smf[];

__device__ __forceinline__ uint32_t smem_u32(const void* p) {
    uint32_t a;
    asm("{ .reg .u64 t; cvta.to.shared.u64 t, %1; cvt.u32.u64 %0, t; }" : "=r"(a) : "l"(p));
    return a;
}
// pack: result.hi = bf16(a), result.lo = bf16(b)
__device__ __forceinline__ uint32_t packbf(float a, float b) {
    uint32_t r;
    asm("cvt.rn.bf16x2.f32 %0, %1, %2;" : "=r"(r) : "f"(a), "f"(b));
    return r;
}
#define STS128(r0, r1, r2, r3, addr) \
    asm volatile("st.shared.v4.b32 [%0], {%1, %2, %3, %4};" \
                 :: "r"(addr), "r"(r0), "r"(r1), "r"(r2), "r"(r3) : "memory")
#define CP_ASYNC16(dst, src, sz) \
    asm volatile("cp.async.cg.shared.global [%0], [%1], 16, %2;" \
                 :: "r"(dst), "l"(src), "r"(sz) : "memory")
#define CP_COMMIT()  asm volatile("cp.async.commit_group;" ::: "memory")
#define CP_WAIT1()   asm volatile("cp.async.wait_group 1;" ::: "memory")
#define CP_WAIT0()   asm volatile("cp.async.wait_group 0;" ::: "memory")

__device__ __forceinline__ void ldmB(uint32_t* b, uint32_t addr) {
    asm volatile("ldmatrix.sync.aligned.m8n8.x2.shared.b16 {%0,%1}, [%2];"
                 : "=r"(b[0]), "=r"(b[1]) : "r"(addr));
}
__device__ __forceinline__ uint32_t ldmB1(uint32_t addr) {
    uint32_t b0;
    asm volatile("ldmatrix.sync.aligned.m8n8.x1.shared.b16 {%0}, [%1];"
                 : "=r"(b0) : "r"(addr));
    return b0;
}
__device__ __forceinline__ void mma16816(float* c, const uint32_t* a,
                                         uint32_t b0, uint32_t b1) {
    asm volatile("mma.sync.aligned.m16n8k16.row.col.f32.bf16.bf16.f32 "
                 "{%0,%1,%2,%3}, {%4,%5,%6,%7}, {%8,%9}, {%0,%1,%2,%3};"
                 : "+f"(c[0]), "+f"(c[1]), "+f"(c[2]), "+f"(c[3])
                 : "r"(a[0]), "r"(a[1]), "r"(a[2]), "r"(a[3]), "r"(b0), "r"(b1));
}
__device__ __forceinline__ uint32_t gpos(int r, int g) {
    return (uint32_t)(g ^ ((r >> 1) & 3));
}

__global__ __launch_bounds__(NT, 2)
void shapelet_kernel(const float* __restrict__ X,
                     const float* __restrict__ q,
                     const int* __restrict__ cumlens,
                     const float* __restrict__ lin_w,
                     const float* __restrict__ lin_b,
                     float* __restrict__ out,
                     long long T, int n_seg)
{
    const uint32_t smb = smem_u32(smf);
    float* cs2p = smf + CS2_OFF / 4;
    float* redf = smf + RED_OFF / 4;
    float* Sbuf = smf;

    const int tid  = threadIdx.x;
    const int w    = tid >> 5;
    const int lane = tid & 31;
    const int l15  = lane & 15;
    const int g_   = lane >> 2;       // fragment row group 0..7
    const int t4   = lane & 3;        // fragment col group 0..3

    const int seg = blockIdx.x;
    const long long c0 = (long long)cumlens[seg];
    int len = cumlens[seg + 1] - (int)c0;
    if (len > TT) len = TT;
    if (len < 0) len = 0;
    const bool aligned = ((c0 & 3) == 0);

    // staging geometry: lane copies 16B unit u_=lane&7 (t = 32w+4u_),
    // d-rows r_=lane>>3 and r_+4 of the chunk, into warp-private padded buffer
    const int u_   = lane & 7;
    const int r_   = lane >> 3;
    const int tcol = 32 * w + 4 * u_;
    const uint32_t xfw = smb + XF_OFF + (uint32_t)w * 1152u
                       + (uint32_t)r_ * 144u + (uint32_t)u_ * 16u;
    int vb = len * 4 - tcol * 4;
    const int sz = vb < 0 ? 0 : (vb > 16 ? 16 : vb);
    const char* gsrc = (const char*)(X + c0 + tcol);

    // ---- stage chunk 0 (warp-private) ----
    if (aligned) {
        CP_ASYNC16(xfw,        gsrc + (long long)(r_) * T * 4,     sz);
        CP_ASYNC16(xfw + 576u, gsrc + (long long)(r_ + 4) * T * 4, sz);
        CP_COMMIT();
    } else {
#pragma unroll
        for (int rr = 0; rr < 2; rr++) {
            float v[4];
#pragma unroll
            for (int f = 0; f < 4; f++) {
                int t = tcol + f;
                v[f] = (t < len) ? X[(long long)(r_ + 4 * rr) * T + c0 + t] : 0.f;
            }
            STS128(__float_as_uint(v[0]), __float_as_uint(v[1]),
                   __float_as_uint(v[2]), __float_as_uint(v[3]), xfw + 576u * rr);
        }
    }

    // ---- Q staging: warp w (w<8) builds B1+B2 for chunk w, + QQ partials ----
    if (w < 8) {
        const int j = lane;
        float qq = 0.f;
        uint32_t h[4], l[4];
#pragma unroll
        for (int k = 0; k < 4; k++) {
            int d = 8 * w + 2 * k;
            float qe = q[d * MLEN + j];
            float qo = q[(d + 1) * MLEN + j];
            qq = fmaf(qe, qe, qq);
            qq = fmaf(qo, qo, qq);
            uint32_t hp = packbf(qo, qe);
            float fe = __uint_as_float(hp << 16);
            float fo = __uint_as_float(hp & 0xffff0000u);
            h[k] = hp;
            l[k] = packbf(qo - fo, qe - fe);
        }
        uint32_t b1 = smb + QB_OFF + (uint32_t)w * 4096u + (uint32_t)j * 64u;
        uint32_t b2 = b1 + 2048u;
#pragma unroll
        for (int g = 0; g < 4; g++)
            STS128(h[0], h[1], h[2], h[3], b1 + gpos(j, g) * 16u);
        STS128(l[0], l[1], l[2], l[3], b2 + gpos(j, 0) * 16u);
        STS128(0u, 0u, 0u, 0u,          b2 + gpos(j, 1) * 16u);
#pragma unroll
        for (int o = 16; o; o >>= 1) qq += __shfl_down_sync(0xffffffffu, qq, o);
        if (lane == 0) redf[40 + w] = qq;
    }
    __syncthreads();     // QB + QQ visible; only block barrier before GEMM
    float QQ = 0.f;
#pragma unroll
    for (int k = 0; k < 8; k++) QQ += redf[40 + k];

    // ---- accumulators: warp owns t in [32w, 32w+32): 2 m x 4 n tiles ----
    float acc[2][4][4];
#pragma unroll
    for (int m = 0; m < 2; m++)
#pragma unroll
        for (int n = 0; n < 4; n++)
#pragma unroll
            for (int k = 0; k < 4; k++) acc[m][n][k] = 0.f;

    float csr[4] = {0.f, 0.f, 0.f, 0.f};   // rows g, 8+g, 16+g, 24+g (local)

#pragma unroll 2
    for (int c = 0; c < NCHUNK; c++) {
        // prefetch next chunk (warp-private)
        if (c + 1 < NCHUNK) {
            uint32_t dst = xfw + (uint32_t)(((c + 1) & 1) * 18432);
            if (aligned) {
                const char* g2 = gsrc + (long long)((c + 1) * DCH) * T * 4;
                CP_ASYNC16(dst,        g2 + (long long)(r_) * T * 4,     sz);
                CP_ASYNC16(dst + 576u, g2 + (long long)(r_ + 4) * T * 4, sz);
                CP_COMMIT();
            } else {
#pragma unroll
                for (int rr = 0; rr < 2; rr++) {
                    float v[4];
#pragma unroll
                    for (int f = 0; f < 4; f++) {
                        int t = tcol + f;
                        v[f] = (t < len) ?
                            X[(long long)((c + 1) * DCH + r_ + 4 * rr) * T + c0 + t] : 0.f;
                    }
                    STS128(__float_as_uint(v[0]), __float_as_uint(v[1]),
                           __float_as_uint(v[2]), __float_as_uint(v[3]), dst + 576u * rr);
                }
            }
        }
        if (aligned) { if (c + 1 < NCHUNK) CP_WAIT1(); else CP_WAIT0(); }
        __syncwarp();    // chunk c data visible warp-wide (incl. scalar path)

        // ---- B fragments for chunk c ----
        const uint32_t qb1 = smb + QB_OFF + (uint32_t)c * 4096u;
        const uint32_t qb2 = qb1 + 2048u;
        uint32_t B1[4][2], B2[4];
#pragma unroll
        for (int n = 0; n < 4; n++) {
            int r = 8 * n + (l15 & 7);
            int g = l15 >> 3;
            ldmB(B1[n], qb1 + (uint32_t)r * 64u + gpos(r, g) * 16u);
            int r2 = 8 * n + (lane & 7);
            B2[n] = ldmB1(qb2 + (uint32_t)r2 * 64u + gpos(r2, 0) * 16u);
        }

        // ---- A fragments straight from f32 staging + MMA ----
        const float* xf = smf + ((c & 1) ? 4608 : 0) + w * 288;   // floats
#pragma unroll
        for (int m = 0; m < 2; m++) {
            const int ta = 16 * m + g_;        // a0/a2 row (local t)
            const int tb = ta + 8;             // a1/a3 row
            float xe0 = xf[(2 * t4) * XFSTR + ta];
            float xo0 = xf[(2 * t4 + 1) * XFSTR + ta];
            float xe1 = xf[(2 * t4) * XFSTR + tb];
            float xo1 = xf[(2 * t4 + 1) * XFSTR + tb];
            csr[2 * m]     = fmaf(xe0, xe0, fmaf(xo0, xo0, csr[2 * m]));
            csr[2 * m + 1] = fmaf(xe1, xe1, fmaf(xo1, xo1, csr[2 * m + 1]));

            uint32_t A[4];
            A[0] = packbf(xo0, xe0);
            A[1] = packbf(xo1, xe1);
            float fe0 = __uint_as_float(A[0] << 16);
            float fo0 = __uint_as_float(A[0] & 0xffff0000u);
            float fe1 = __uint_as_float(A[1] << 16);
            float fo1 = __uint_as_float(A[1] & 0xffff0000u);
            A[2] = packbf(xo0 - fo0, xe0 - fe0);
            A[3] = packbf(xo1 - fo1, xe1 - fe1);

#pragma unroll
            for (int n = 0; n < 4; n++) {
                mma16816(acc[m][n], A, B1[n][0], B1[n][1]);
                mma16816(acc[m][n], A, B2[n], 0u);
            }
        }
        __syncwarp();    // all lanes done reading staging buf before reuse
    }

    // ---- cs2: reduce across the 4-lane t4 groups, write per-row sums ----
#pragma unroll
    for (int k = 0; k < 4; k++) {
        csr[k] += __shfl_xor_sync(0xffffffffu, csr[k], 1);
        csr[k] += __shfl_xor_sync(0xffffffffu, csr[k], 2);
    }
    if (t4 == 0) {
        cs2p[32 * w + g_]      = csr[0];
        cs2p[32 * w + 8 + g_]  = csr[1];
        cs2p[32 * w + 16 + g_] = csr[2];
        cs2p[32 * w + 24 + g_] = csr[3];
    }
    __syncthreads();       // all warps done with XF/QB; Sbuf alias safe

    // ---- scatter S fragments to Sbuf[512][33] ----
    {
        const int rbase = 32 * w + g_;
        const int cbase = 2 * t4;
#pragma unroll
        for (int m = 0; m < 2; m++) {
#pragma unroll
            for (int n = 0; n < 4; n++) {
                int r = rbase + 16 * m;
                int cc = cbase + 8 * n;
                Sbuf[r * SSTRIDE + cc]           = acc[m][n][0];
                Sbuf[r * SSTRIDE + cc + 1]       = acc[m][n][1];
                Sbuf[(r + 8) * SSTRIDE + cc]     = acc[m][n][2];
                Sbuf[(r + 8) * SSTRIDE + cc + 1] = acc[m][n][3];
            }
        }
    }
    __syncthreads();

    // ---- gather: QX[p], dist, segment min ----
    const int nwin = len - MLEN + 1;
    float lmin = 3e38f;
    if (tid < nwin) {
        float qx = 0.f, xx = 0.f;
#pragma unroll
        for (int j = 0; j < MLEN; j++) {
            qx += Sbuf[(tid + j) * SSTRIDE + j];
            xx += cs2p[tid + j];
        }
        lmin = QQ + xx - 2.f * qx;
    }
#pragma unroll
    for (int o = 16; o; o >>= 1) lmin = fminf(lmin, __shfl_down_sync(0xffffffffu, lmin, o));
    __syncthreads();
    if (lane == 0) redf[w] = lmin;
    __syncthreads();
    if (tid == 0) {
        float m = redf[0];
#pragma unroll
        for (int ww = 1; ww < NT / 32; ww++) m = fminf(m, redf[ww]);
        g_mins[seg] = m;
    }

    // ---- last-block-done epilogue ----
    int* flagp = (int*)(redf + 33);
    __threadfence();
    __syncthreads();
    if (tid == 0) {
        int old = atomicAdd(&g_count, 1);
        *flagp = (old == gridDim.x - 1) ? 1 : 0;
    }
    __syncthreads();
    if (!*flagp) return;
    __threadfence();

    float lo = 3e38f, hi = -3e38f;
    for (int i = tid; i < n_seg; i += NT) {
        float v = g_mins[i];
        lo = fminf(lo, v);
        hi = fmaxf(hi, v);
    }
#pragma unroll
    for (int o = 16; o; o >>= 1) {
        lo = fminf(lo, __shfl_down_sync(0xffffffffu, lo, o));
        hi = fmaxf(hi, __shfl_down_sync(0xffffffffu, hi, o));
    }
    __syncthreads();
    if (lane == 0) { redf[w] = lo; redf[16 + w] = hi; }
    __syncthreads();
    if (tid == 0) {
        float l = redf[0], h = redf[16];
#pragma unroll
        for (int ww = 1; ww < NT / 32; ww++) { l = fminf(l, redf[ww]); h = fmaxf(h, redf[16 + ww]); }
        redf[34] = l; redf[35] = h;
        g_count = 0;
    }
    __syncthreads();
    const float flo = redf[34], fhi = redf[35];
    const float w0 = lin_w[0], w1 = lin_w[1];
    const float b0 = lin_b[0], b1 = lin_b[1];
    const float inv = 1.f / (fhi - flo + 1e-16f);
    for (int i = tid; i < n_seg; i += NT) {
        float s = (g_mins[i] - flo) * inv;
        out[2 * i]     = fmaf(s, w0, b0);
        out[2 * i + 1] = fmaf(s, w1, b1);
    }
}

extern "C" void kernel_launch(void* const* d_in, const int* in_sizes, int n_in,
                              void* d_out, int out_size)
{
    const float* X   = (const float*)d_in[0];
    const float* q   = (const float*)d_in[1];
    const float* lw  = (const float*)d_in[2];
    const float* lb  = (const float*)d_in[3];
    const int*   cum = (const int*)d_in[4];

    const int n_seg = in_sizes[4] - 1;
    const long long T = (long long)in_sizes[0] / DFEAT;

    cudaFuncSetAttribute(shapelet_kernel,
                         cudaFuncAttributeMaxDynamicSharedMemorySize, SMEM_BYTES);

    shapelet_kernel<<<n_seg, NT, SMEM_BYTES>>>(X, q, cum, lw, lb, (float*)d_out, T, n_seg);
}

// round 11
// speedup vs baseline: 1.3676x; 1.1552x over previous
#include <cuda_runtime.h>
#include <cstdint>

// ShapeletNet via HMMA bf16-split GEMM, 16-d chunks, 3-MMA split (no wasted k).
// cp.async f32 staging (warp-private, double-buffered); A fragments built in
// registers from staging LDS. B tables qh/ql: 32B rows padded to 48B stride
// (conflict-free ldmatrix + STS). Main loop: 1-2 __syncwarp per chunk.
// Math per 16d: xh*qh (g0g1) + xl*qh (g2g3) + xh*ql  (xl*ql dropped ~2^-16).
// dist[p] = QQ + XX[p] - 2*QX[p]; per-segment min; last-done block: scale+Linear.

#define DFEAT 64
#define MLEN 32
#define TT 512
#define NT 512
#define DCH 16
#define NCHUNK 4
#define SSTRIDE 33
#define XFSTR 36            // staging row stride in floats

// byte offsets in dynamic smem
#define XF_OFF   0          // 2 bufs x 16 warps x 16 rows x 144B = 73728
#define QB_OFF   73728      // 4 chunks x (qh 1536 + ql 1536) = 12288 -> 86016
#define CS2_OFF  86016      // 512 f32 -> 88064
#define RED_OFF  88064      // 64 f32  -> 88320
#define SMEM_BYTES 88320
// Sbuf[0, 67584) aliases XF after the GEMM completes

__device__ float g_mins[8192];
__device__ int   g_count;

extern __shared__ __align__(1024) float smf[];

__device__ __forceinline__ uint32_t smem_u32(const void* p) {
    uint32_t a;
    asm("{ .reg .u64 t; cvta.to.shared.u64 t, %1; cvt.u32.u64 %0, t; }" : "=r"(a) : "l"(p));
    return a;
}
// pack: result.hi = bf16(a), result.lo = bf16(b)
__device__ __forceinline__ uint32_t packbf(float a, float b) {
    uint32_t r;
    asm("cvt.rn.bf16x2.f32 %0, %1, %2;" : "=r"(r) : "f"(a), "f"(b));
    return r;
}
#define STS128(r0, r1, r2, r3, addr) \
    asm volatile("st.shared.v4.b32 [%0], {%1, %2, %3, %4};" \
                 :: "r"(addr), "r"(r0), "r"(r1), "r"(r2), "r"(r3) : "memory")
#define CP_ASYNC16(dst, src, sz) \
    asm volatile("cp.async.cg.shared.global [%0], [%1], 16, %2;" \
                 :: "r"(dst), "l"(src), "r"(sz) : "memory")
#define CP_COMMIT()  asm volatile("cp.async.commit_group;" ::: "memory")
#define CP_WAIT1()   asm volatile("cp.async.wait_group 1;" ::: "memory")
#define CP_WAIT0()   asm volatile("cp.async.wait_group 0;" ::: "memory")

__device__ __forceinline__ void ldmB(uint32_t* b, uint32_t addr) {
    asm volatile("ldmatrix.sync.aligned.m8n8.x2.shared.b16 {%0,%1}, [%2];"
                 : "=r"(b[0]), "=r"(b[1]) : "r"(addr));
}
__device__ __forceinline__ void mma16816(float* c, const uint32_t* a,
                                         uint32_t b0, uint32_t b1) {
    asm volatile("mma.sync.aligned.m16n8k16.row.col.f32.bf16.bf16.f32 "
                 "{%0,%1,%2,%3}, {%4,%5,%6,%7}, {%8,%9}, {%0,%1,%2,%3};"
                 : "+f"(c[0]), "+f"(c[1]), "+f"(c[2]), "+f"(c[3])
                 : "r"(a[0]), "r"(a[1]), "r"(a[2]), "r"(a[3]), "r"(b0), "r"(b1));
}

__global__ __launch_bounds__(NT, 2)
void shapelet_kernel(const float* __restrict__ X,
                     const float* __restrict__ q,
                     const int* __restrict__ cumlens,
                     const float* __restrict__ lin_w,
                     const float* __restrict__ lin_b,
                     float* __restrict__ out,
                     long long T, int n_seg)
{
    const uint32_t smb = smem_u32(smf);
    float* cs2p = smf + CS2_OFF / 4;
    float* redf = smf + RED_OFF / 4;
    float* Sbuf = smf;

    const int tid  = threadIdx.x;
    const int w    = tid >> 5;
    const int lane = tid & 31;
    const int l15  = lane & 15;
    const int g_   = lane >> 2;       // fragment row group 0..7
    const int t4   = lane & 3;        // fragment col group 0..3

    const int seg = blockIdx.x;
    const long long c0 = (long long)cumlens[seg];
    int len = cumlens[seg + 1] - (int)c0;
    if (len > TT) len = TT;
    if (len < 0) len = 0;
    const bool aligned = ((c0 & 3) == 0);

    // staging: lane copies 16B unit u_=lane&7 (t = 32w+4u_), d-rows r_+4k, k=0..3
    const int u_   = lane & 7;
    const int r_   = lane >> 3;
    const int tcol = 32 * w + 4 * u_;
    const uint32_t xfw = smb + XF_OFF + (uint32_t)w * 2304u
                       + (uint32_t)r_ * 144u + (uint32_t)u_ * 16u;
    int vb = len * 4 - tcol * 4;
    const int sz = vb < 0 ? 0 : (vb > 16 ? 16 : vb);
    const char* gsrc = (const char*)(X + c0 + tcol);

    // ---- stage chunk 0 (warp-private) ----
    if (aligned) {
#pragma unroll
        for (int k = 0; k < 4; k++)
            CP_ASYNC16(xfw + (uint32_t)k * 576u,
                       gsrc + (long long)(r_ + 4 * k) * T * 4, sz);
        CP_COMMIT();
    } else {
#pragma unroll
        for (int rr = 0; rr < 4; rr++) {
            float v[4];
#pragma unroll
            for (int f = 0; f < 4; f++) {
                int t = tcol + f;
                v[f] = (t < len) ? X[(long long)(r_ + 4 * rr) * T + c0 + t] : 0.f;
            }
            STS128(__float_as_uint(v[0]), __float_as_uint(v[1]),
                   __float_as_uint(v[2]), __float_as_uint(v[3]), xfw + 576u * rr);
        }
    }

    // ---- Q staging: warp w (w<4) builds qh+ql tables for chunk w, + QQ ----
    if (w < 4) {
        const int j = lane;
        float qq = 0.f;
        uint32_t h[8], l[8];
#pragma unroll
        for (int k = 0; k < 8; k++) {
            int d = 16 * w + 2 * k;
            float qe = q[d * MLEN + j];
            float qo = q[(d + 1) * MLEN + j];
            qq = fmaf(qe, qe, qq);
            qq = fmaf(qo, qo, qq);
            uint32_t hp = packbf(qo, qe);
            float fe = __uint_as_float(hp << 16);
            float fo = __uint_as_float(hp & 0xffff0000u);
            h[k] = hp;
            l[k] = packbf(qo - fo, qe - fe);
        }
        uint32_t qh = smb + QB_OFF + (uint32_t)w * 3072u + (uint32_t)j * 48u;
        uint32_t ql = qh + 1536u;
        STS128(h[0], h[1], h[2], h[3], qh);
        STS128(h[4], h[5], h[6], h[7], qh + 16u);
        STS128(l[0], l[1], l[2], l[3], ql);
        STS128(l[4], l[5], l[6], l[7], ql + 16u);
#pragma unroll
        for (int o = 16; o; o >>= 1) qq += __shfl_down_sync(0xffffffffu, qq, o);
        if (lane == 0) redf[40 + w] = qq;
    }
    __syncthreads();     // QB + QQ visible; only block barrier before GEMM
    float QQ = redf[40] + redf[41] + redf[42] + redf[43];

    // ---- accumulators: warp owns t in [32w, 32w+32): 2 m x 4 n tiles ----
    float acc[2][4][4];
#pragma unroll
    for (int m = 0; m < 2; m++)
#pragma unroll
        for (int n = 0; n < 4; n++)
#pragma unroll
            for (int k = 0; k < 4; k++) acc[m][n][k] = 0.f;

    float csr[4] = {0.f, 0.f, 0.f, 0.f};

#pragma unroll 2
    for (int c = 0; c < NCHUNK; c++) {
        // prefetch next chunk (warp-private)
        if (c + 1 < NCHUNK) {
            uint32_t dst = xfw + (uint32_t)(((c + 1) & 1) * 36864);
            if (aligned) {
                const char* g2 = gsrc + (long long)((c + 1) * DCH) * T * 4;
#pragma unroll
                for (int k = 0; k < 4; k++)
                    CP_ASYNC16(dst + (uint32_t)k * 576u,
                               g2 + (long long)(r_ + 4 * k) * T * 4, sz);
                CP_COMMIT();
            } else {
#pragma unroll
                for (int rr = 0; rr < 4; rr++) {
                    float v[4];
#pragma unroll
                    for (int f = 0; f < 4; f++) {
                        int t = tcol + f;
                        v[f] = (t < len) ?
                            X[(long long)((c + 1) * DCH + r_ + 4 * rr) * T + c0 + t] : 0.f;
                    }
                    STS128(__float_as_uint(v[0]), __float_as_uint(v[1]),
                           __float_as_uint(v[2]), __float_as_uint(v[3]), dst + 576u * rr);
                }
            }
        }
        if (aligned) { if (c + 1 < NCHUNK) CP_WAIT1(); else CP_WAIT0(); }
        __syncwarp();

        // ---- B fragments for chunk c: qh + ql, 4 n-tiles each ----
        const uint32_t qh = smb + QB_OFF + (uint32_t)c * 3072u;
        const uint32_t ql = qh + 1536u;
        uint32_t BH[4][2], BL[4][2];
#pragma unroll
        for (int n = 0; n < 4; n++) {
            uint32_t ro = (uint32_t)(8 * n + (l15 & 7)) * 48u + (uint32_t)(l15 >> 3) * 16u;
            ldmB(BH[n], qh + ro);
            ldmB(BL[n], ql + ro);
        }

        // ---- A fragments straight from f32 staging + MMA ----
        const float* xf = smf + ((c & 1) ? 9216 : 0) + w * 576;
#pragma unroll
        for (int m = 0; m < 2; m++) {
            const int ta = 16 * m + g_;
            const int tb = ta + 8;
            float xe0  = xf[(2 * t4) * XFSTR + ta];
            float xo0  = xf[(2 * t4 + 1) * XFSTR + ta];
            float xe1  = xf[(2 * t4) * XFSTR + tb];
            float xo1  = xf[(2 * t4 + 1) * XFSTR + tb];
            float xe0b = xf[(2 * t4 + 8) * XFSTR + ta];
            float xo0b = xf[(2 * t4 + 9) * XFSTR + ta];
            float xe1b = xf[(2 * t4 + 8) * XFSTR + tb];
            float xo1b = xf[(2 * t4 + 9) * XFSTR + tb];
            csr[2 * m]     = fmaf(xe0, xe0, fmaf(xo0, xo0,
                             fmaf(xe0b, xe0b, fmaf(xo0b, xo0b, csr[2 * m]))));
            csr[2 * m + 1] = fmaf(xe1, xe1, fmaf(xo1, xo1,
                             fmaf(xe1b, xe1b, fmaf(xo1b, xo1b, csr[2 * m + 1]))));

            uint32_t Ah[4], Al[4];
            Ah[0] = packbf(xo0, xe0);
            Ah[1] = packbf(xo1, xe1);
            Ah[2] = packbf(xo0b, xe0b);
            Ah[3] = packbf(xo1b, xe1b);
            {
                float fe0 = __uint_as_float(Ah[0] << 16);
                float fo0 = __uint_as_float(Ah[0] & 0xffff0000u);
                float fe1 = __uint_as_float(Ah[1] << 16);
                float fo1 = __uint_as_float(Ah[1] & 0xffff0000u);
                Al[0] = packbf(xo0 - fo0, xe0 - fe0);
                Al[1] = packbf(xo1 - fo1, xe1 - fe1);
                float fe2 = __uint_as_float(Ah[2] << 16);
                float fo2 = __uint_as_float(Ah[2] & 0xffff0000u);
                float fe3 = __uint_as_float(Ah[3] << 16);
                float fo3 = __uint_as_float(Ah[3] & 0xffff0000u);
                Al[2] = packbf(xo0b - fo2, xe0b - fe2);
                Al[3] = packbf(xo1b - fo3, xe1b - fe3);
            }
#pragma unroll
            for (int n = 0; n < 4; n++) {
                mma16816(acc[m][n], Ah, BH[n][0], BH[n][1]);
                mma16816(acc[m][n], Al, BH[n][0], BH[n][1]);
                mma16816(acc[m][n], Ah, BL[n][0], BL[n][1]);
            }
        }
        __syncwarp();    // all lanes done reading staging buf before reuse
    }

    // ---- cs2: reduce across the 4-lane t4 groups, write per-row sums ----
#pragma unroll
    for (int k = 0; k < 4; k++) {
        csr[k] += __shfl_xor_sync(0xffffffffu, csr[k], 1);
        csr[k] += __shfl_xor_sync(0xffffffffu, csr[k], 2);
    }
    if (t4 == 0) {
        cs2p[32 * w + g_]      = csr[0];
        cs2p[32 * w + 8 + g_]  = csr[1];
        cs2p[32 * w + 16 + g_] = csr[2];
        cs2p[32 * w + 24 + g_] = csr[3];
    }
    __syncthreads();       // all warps done with XF/QB; Sbuf alias safe

    // ---- scatter S fragments to Sbuf[512][33] ----
    {
        const int rbase = 32 * w + g_;
        const int cbase = 2 * t4;
#pragma unroll
        for (int m = 0; m < 2; m++) {
#pragma unroll
            for (int n = 0; n < 4; n++) {
                int r = rbase + 16 * m;
                int cc = cbase + 8 * n;
                Sbuf[r * SSTRIDE + cc]           = acc[m][n][0];
                Sbuf[r * SSTRIDE + cc + 1]       = acc[m][n][1];
                Sbuf[(r + 8) * SSTRIDE + cc]     = acc[m][n][2];
                Sbuf[(r + 8) * SSTRIDE + cc + 1] = acc[m][n][3];
            }
        }
    }
    __syncthreads();

    // ---- gather: QX[p], dist, segment min ----
    const int nwin = len - MLEN + 1;
    float lmin = 3e38f;
    if (tid < nwin) {
        float qx = 0.f, xx = 0.f;
#pragma unroll
        for (int j = 0; j < MLEN; j++) {
            qx += Sbuf[(tid + j) * SSTRIDE + j];
            xx += cs2p[tid + j];
        }
        lmin = QQ + xx - 2.f * qx;
    }
#pragma unroll
    for (int o = 16; o; o >>= 1) lmin = fminf(lmin, __shfl_down_sync(0xffffffffu, lmin, o));
    __syncthreads();
    if (lane == 0) redf[w] = lmin;
    __syncthreads();
    if (tid == 0) {
        float m = redf[0];
#pragma unroll
        for (int ww = 1; ww < NT / 32; ww++) m = fminf(m, redf[ww]);
        g_mins[seg] = m;
    }

    // ---- last-block-done epilogue ----
    int* flagp = (int*)(redf + 33);
    __threadfence();
    __syncthreads();
    if (tid == 0) {
        int old = atomicAdd(&g_count, 1);
        *flagp = (old == gridDim.x - 1) ? 1 : 0;
    }
    __syncthreads();
    if (!*flagp) return;
    __threadfence();

    float lo = 3e38f, hi = -3e38f;
    for (int i = tid; i < n_seg; i += NT) {
        float v = g_mins[i];
        lo = fminf(lo, v);
        hi = fmaxf(hi, v);
    }
#pragma unroll
    for (int o = 16; o; o >>= 1) {
        lo = fminf(lo, __shfl_down_sync(0xffffffffu, lo, o));
        hi = fmaxf(hi, __shfl_down_sync(0xffffffffu, hi, o));
    }
    __syncthreads();
    if (lane == 0) { redf[w] = lo; redf[16 + w] = hi; }
    __syncthreads();
    if (tid == 0) {
        float l = redf[0], h = redf[16];
#pragma unroll
        for (int ww = 1; ww < NT / 32; ww++) { l = fminf(l, redf[ww]); h = fmaxf(h, redf[16 + ww]); }
        redf[34] = l; redf[35] = h;
        g_count = 0;
    }
    __syncthreads();
    const float flo = redf[34], fhi = redf[35];
    const float w0 = lin_w[0], w1 = lin_w[1];
    const float b0 = lin_b[0], b1 = lin_b[1];
    const float inv = 1.f / (fhi - flo + 1e-16f);
    for (int i = tid; i < n_seg; i += NT) {
        float s = (g_mins[i] - flo) * inv;
        out[2 * i]     = fmaf(s, w0, b0);
        out[2 * i + 1] = fmaf(s, w1, b1);
    }
}

extern "C" void kernel_launch(void* const* d_in, const int* in_sizes, int n_in,
                              void* d_out, int out_size)
{
    const float* X   = (const float*)d_in[0];
    const float* q   = (const float*)d_in[1];
    const float* lw  = (const float*)d_in[2];
    const float* lb  = (const float*)d_in[3];
    const int*   cum = (const int*)d_in[4];

    const int n_seg = in_sizes[4] - 1;
    const long long T = (long long)in_sizes[0] / DFEAT;

    cudaFuncSetAttribute(shapelet_kernel,
                         cudaFuncAttributeMaxDynamicSharedMemorySize, SMEM_BYTES);

    shapelet_kernel<<<n_seg, NT, SMEM_BYTES>>>(X, q, cum, lw, lb, (float*)d_out, T, n_seg);
}